// round 10
// baseline (speedup 1.0000x reference)
#include <cuda_runtime.h>
#include <cuda_bf16.h>
#include <cstdint>
#include <cstddef>

#define Bb 2048
#define Nn 200
#define Ee 128
#define ROWS (Bb * Nn)   // 409600

// ---------------------------------------------------------------------------
// Static device scratch (no cudaMalloc allowed)
// ---------------------------------------------------------------------------
__device__ float g_K4 [(size_t)ROWS * 128];  // x @ Wk.T     (B*N,128)
__device__ float g_V4 [(size_t)ROWS * 128];  // x @ Wv.T
__device__ float g_Kx [(size_t)ROWS * 128];  // x @ WprjK.T
__device__ float g_Xq2[(size_t)ROWS * 128];  // x @ Wq[:,128:256].T  ("last" q contribution)
__device__ float g_Xq3[(size_t)ROWS * 128];  // x @ Wq[:,256:384].T  ("first" q contribution)
__device__ float g_Wcat[128 * 640];          // k-major concat weight for the big GEMM
__device__ float g_WoT [128 * 128];          // Wo transposed (k-major)
__device__ float g_qh  [Bb * 128];           // hinit @ Wq[:,0:128].T
__device__ float g_qlast0 [128];             // initK @ Wq[:,128:256].T
__device__ float g_qfirst0[128];             // initV @ Wq[:,256:384].T
__device__ unsigned int g_fk0[Nn];           // per-step folded threefry keys
__device__ unsigned int g_fk1[Nn];

// ---------------------------------------------------------------------------
// Threefry-2x32 (20 rounds) — bitwise identical to JAX
// ---------------------------------------------------------------------------
__device__ __forceinline__ unsigned int rotl32(unsigned int v, int r) {
    return (v << r) | (v >> (32 - r));
}

__device__ __forceinline__ void tf2x32(unsigned int k0, unsigned int k1,
                                       unsigned int x0, unsigned int x1,
                                       unsigned int& o0, unsigned int& o1) {
    unsigned int ks[3];
    ks[0] = k0; ks[1] = k1; ks[2] = k0 ^ k1 ^ 0x1BD11BDAu;
    x0 += ks[0]; x1 += ks[1];
    const int R1[4] = {13, 15, 26, 6};
    const int R2[4] = {17, 29, 16, 24};
#pragma unroll
    for (int g = 0; g < 5; g++) {
        const int* R = (g & 1) ? R2 : R1;
#pragma unroll
        for (int j = 0; j < 4; j++) {
            x0 += x1;
            x1 = rotl32(x1, R[j]);
            x1 ^= x0;
        }
        x0 += ks[(g + 1) % 3];
        x1 += ks[(g + 2) % 3] + (unsigned int)(g + 1);
    }
    o0 = x0; o1 = x1;
}

// ---------------------------------------------------------------------------
// XLA EmitFastTanh (f32) — matches XLA GPU's tanh lowering
// ---------------------------------------------------------------------------
__device__ __forceinline__ float fast_tanh(float x) {
    if (fabsf(x) < 0.0004f) return x;
    float xc = fminf(fmaxf(x, -9.0f), 9.0f);
    float x2 = xc * xc;
    float num = -2.76076847742355e-16f;
    num = num * x2 + 2.00018790482477e-13f;
    num = num * x2 + -8.60467152213735e-11f;
    num = num * x2 + 5.12229709037114e-08f;
    num = num * x2 + 1.48572235717979e-05f;
    num = num * x2 + 6.37261928875436e-04f;
    num = num * x2 + 4.89352455891786e-03f;
    num = num * xc;
    float den = 1.19825839466702e-06f;
    den = den * x2 + 1.18534705686654e-04f;
    den = den * x2 + 2.26843463243900e-03f;
    den = den * x2 + 4.89352518554385e-03f;
    return num / den;
}

// ---------------------------------------------------------------------------
// Kernel 1: build Wcat / WoT / init-q vectors / per-step folded keys
// ---------------------------------------------------------------------------
__global__ void prep_kernel(const float* __restrict__ Wk, const float* __restrict__ Wv,
                            const float* __restrict__ WprjK, const float* __restrict__ Wq,
                            const float* __restrict__ Wo, const float* __restrict__ initK,
                            const float* __restrict__ initV) {
    int tid = blockIdx.x * blockDim.x + threadIdx.x;
    int nthr = gridDim.x * blockDim.x;

    // Wcat[k][c], k-major rows of 640 output cols
    for (int idx = tid; idx < 128 * 640; idx += nthr) {
        int k = idx / 640, c = idx % 640;
        float v;
        if      (c < 128) v = Wk[c * 128 + k];
        else if (c < 256) v = Wv[(c - 128) * 128 + k];
        else if (c < 384) v = WprjK[(c - 256) * 128 + k];
        else if (c < 512) v = Wq[(size_t)(c - 384) * 384 + 128 + k];
        else              v = Wq[(size_t)(c - 512) * 384 + 256 + k];
        g_Wcat[idx] = v;
    }
    for (int idx = tid; idx < 128 * 128; idx += nthr) {
        int k = idx >> 7, e = idx & 127;
        g_WoT[idx] = Wo[e * 128 + k];
    }
    for (int o = tid; o < 128; o += nthr) {
        float a = 0.f, b = 0.f;
        for (int k = 0; k < 128; k++) {
            a += initK[k] * Wq[(size_t)o * 384 + 128 + k];
            b += initV[k] * Wq[(size_t)o * 384 + 256 + k];
        }
        g_qlast0[o] = a;
        g_qfirst0[o] = b;
    }
    // folded keys: fold_in(key(42), i) = threefry_block(key=(0,42), data=(0,i))
    for (int i = tid; i < Nn; i += nthr) {
        unsigned int o0, o1;
        tf2x32(0u, 42u, 0u, (unsigned int)i, o0, o1);
        g_fk0[i] = o0; g_fk1[i] = o1;
    }
}

// ---------------------------------------------------------------------------
// Kernel 2: big fused GEMM  C(409600,640) = x(409600,128) @ Wcat(128,640)
// Block tile 128(M) x 64(N), BK=32, 256 threads, thread tile 8x4.
// ---------------------------------------------------------------------------
__global__ void __launch_bounds__(256) gemm_kernel(const float* __restrict__ A) {
    __shared__ float sA[128][33];
    __shared__ float sW[32][64];
    int bn = blockIdx.x, bm = blockIdx.y;
    int t = threadIdx.x;
    int tx = t & 15, ty = t >> 4;   // tx: col group (4 cols), ty: row group (8 rows)
    float acc[8][4];
#pragma unroll
    for (int i = 0; i < 8; i++)
#pragma unroll
        for (int j = 0; j < 4; j++) acc[i][j] = 0.f;

    int mbase = bm * 128;
    for (int kb = 0; kb < 128; kb += 32) {
        // A tile: 128 rows x 32 k
#pragma unroll
        for (int rr = 0; rr < 4; rr++) {
            int r = (t >> 3) + rr * 32;
            int c4 = (t & 7) * 4;
            float4 v = *(const float4*)&A[(size_t)(mbase + r) * 128 + kb + c4];
            sA[r][c4 + 0] = v.x; sA[r][c4 + 1] = v.y;
            sA[r][c4 + 2] = v.z; sA[r][c4 + 3] = v.w;
        }
        // W tile: 32 k x 64 cols
#pragma unroll
        for (int rr = 0; rr < 2; rr++) {
            int kr = (t >> 4) + rr * 16;
            int c4 = (t & 15) * 4;
            *(float4*)&sW[kr][c4] =
                *(const float4*)&g_Wcat[(size_t)(kb + kr) * 640 + bn * 64 + c4];
        }
        __syncthreads();
#pragma unroll
        for (int kk = 0; kk < 32; kk++) {
            float a_[8];
#pragma unroll
            for (int i = 0; i < 8; i++) a_[i] = sA[ty * 8 + i][kk];
            float4 wv = *(const float4*)&sW[kk][tx * 4];
#pragma unroll
            for (int i = 0; i < 8; i++) {
                acc[i][0] += a_[i] * wv.x;
                acc[i][1] += a_[i] * wv.y;
                acc[i][2] += a_[i] * wv.z;
                acc[i][3] += a_[i] * wv.w;
            }
        }
        __syncthreads();
    }
    int colg = bn * 64 + tx * 4;
    float* out = (colg < 128) ? g_K4 : (colg < 256) ? g_V4
               : (colg < 384) ? g_Kx : (colg < 512) ? g_Xq2 : g_Xq3;
    int col = colg & 127;
#pragma unroll
    for (int i = 0; i < 8; i++) {
        float4 v = make_float4(acc[i][0], acc[i][1], acc[i][2], acc[i][3]);
        *(float4*)&out[(size_t)(mbase + ty * 8 + i) * 128 + col] = v;
    }
}

// ---------------------------------------------------------------------------
// Kernel 3: hinit = mean_n x[b,n,:] ; qh = hinit @ Wq[:,0:128].T
// ---------------------------------------------------------------------------
__global__ void hinit_qh_kernel(const float* __restrict__ x, const float* __restrict__ Wq) {
    int b = blockIdx.x, t = threadIdx.x;  // 128 threads
    __shared__ float sh[128];
    const float* xb = x + (size_t)b * Nn * Ee;
    float s = 0.f;
    for (int n = 0; n < Nn; n++) s += xb[(size_t)n * Ee + t];
    sh[t] = s / 200.0f;
    __syncthreads();
    float acc = 0.f;
    const float* wrow = Wq + (size_t)t * 384;
    for (int k = 0; k < 128; k++) acc += sh[k] * wrow[k];
    g_qh[b * 128 + t] = acc;
}

// ---------------------------------------------------------------------------
// Kernel 4: persistent decode — one block per batch row, 200 steps
// ---------------------------------------------------------------------------
__global__ void __launch_bounds__(256) decode_kernel(void* outp, int mode,
                                                     const unsigned int* __restrict__ clipb) {
    int b = blockIdx.x, t = threadIdx.x;
    int lane = t & 31, w = t >> 5;   // 8 warps, warp = head

    __shared__ float sQ[128], sQv[128], sCtx[128];
    __shared__ unsigned char sMask[Nn];
    __shared__ float rv[256];
    __shared__ int   ri[256];
    __shared__ int   sLast, sFirst, sSel;
    __shared__ float sChosen, sM, sLogp;

    // clip: handle int32 or float32 storage
    unsigned int cbits = *clipb;
    float cf = __uint_as_float(cbits);
    float clipv = (cf > 1e-6f && cf < 1e6f) ? cf : (float)(int)cbits;
    const float NEGINF = __int_as_float(0xff800000);
    const float TINY = 1.17549435e-38f;

    for (int n = t; n < Nn; n += 256) sMask[n] = 0;
    if (t == 0) { sLast = -1; sFirst = -1; sLogp = 0.f; }
    __syncthreads();

    for (int i = 0; i < Nn; i++) {
        // ---- A: q = qh + Xq2[last] + Xq3[first] (init vectors before step 0)
        if (t < 128) {
            float v = g_qh[b * 128 + t];
            v += (sLast  < 0) ? g_qlast0[t]  : g_Xq2[((size_t)(b * Nn + sLast )) * 128 + t];
            v += (sFirst < 0) ? g_qfirst0[t] : g_Xq3[((size_t)(b * Nn + sFirst)) * 128 + t];
            sQ[t] = v;
        }
        __syncthreads();

        // ---- B: attention per head (warp). U = (q·K)*0.25, softmax, ctx = att·V
        {
            int h = w;
            float qd[16];
#pragma unroll
            for (int d = 0; d < 16; d++) qd[d] = sQ[h * 16 + d];
            float v[7];
            float m = NEGINF;
#pragma unroll
            for (int j = 0; j < 7; j++) {
                int n = j * 32 + lane;
                float val = NEGINF;
                if (n < Nn && !sMask[n]) {
                    const float4* kp =
                        (const float4*)&g_K4[((size_t)(b * Nn + n)) * 128 + h * 16];
                    float acc = 0.f;
#pragma unroll
                    for (int q4 = 0; q4 < 4; q4++) {
                        float4 kv = kp[q4];
                        acc += qd[q4 * 4 + 0] * kv.x + qd[q4 * 4 + 1] * kv.y
                             + qd[q4 * 4 + 2] * kv.z + qd[q4 * 4 + 3] * kv.w;
                    }
                    val = acc * 0.25f;
                }
                v[j] = val;
                m = fmaxf(m, val);
            }
#pragma unroll
            for (int off = 16; off; off >>= 1)
                m = fmaxf(m, __shfl_xor_sync(0xffffffffu, m, off));
            float e[7], s = 0.f;
#pragma unroll
            for (int j = 0; j < 7; j++) { e[j] = expf(v[j] - m); s += e[j]; }
#pragma unroll
            for (int off = 16; off; off >>= 1)
                s += __shfl_xor_sync(0xffffffffu, s, off);

            float acc[16];
#pragma unroll
            for (int d = 0; d < 16; d++) acc[d] = 0.f;
#pragma unroll
            for (int j = 0; j < 7; j++) {
                int n = j * 32 + lane;
                if (n < Nn && e[j] != 0.f) {
                    float att = e[j] / s;
                    const float4* vp =
                        (const float4*)&g_V4[((size_t)(b * Nn + n)) * 128 + h * 16];
#pragma unroll
                    for (int q4 = 0; q4 < 4; q4++) {
                        float4 vv = vp[q4];
                        acc[q4 * 4 + 0] += att * vv.x;
                        acc[q4 * 4 + 1] += att * vv.y;
                        acc[q4 * 4 + 2] += att * vv.z;
                        acc[q4 * 4 + 3] += att * vv.w;
                    }
                }
            }
#pragma unroll
            for (int d = 0; d < 16; d++) {
                float r = acc[d];
#pragma unroll
                for (int off = 16; off; off >>= 1)
                    r += __shfl_xor_sync(0xffffffffu, r, off);
                if (lane == 0) sCtx[h * 16 + d] = r;
            }
        }
        __syncthreads();

        // ---- C: qv = ctx @ Wo.T
        if (t < 128) {
            float acc = 0.f;
            for (int k = 0; k < 128; k++) acc += sCtx[k] * g_WoT[k * 128 + t];
            sQv[t] = acc;
        }
        __syncthreads();

        // ---- D: pointer logits + Gumbel noise
        float logit = NEGINF, val = NEGINF;
        int myn = 0x7fffffff;
        if (t < Nn) {
            myn = t;
            if (!sMask[t]) {
                const float4* kx = (const float4*)&g_Kx[((size_t)(b * Nn + t)) * 128];
                float acc = 0.f;
#pragma unroll 8
                for (int q4 = 0; q4 < 32; q4++) {
                    float4 kv = kx[q4];
                    acc += sQv[q4 * 4 + 0] * kv.x + sQv[q4 * 4 + 1] * kv.y
                         + sQv[q4 * 4 + 2] * kv.z + sQv[q4 * 4 + 3] * kv.w;
                }
                logit = clipv * fast_tanh(acc / 128.0f);
                // gumbel: partitionable threefry bits, count = (0, b*N + n)
                unsigned int o0, o1;
                tf2x32(g_fk0[i], g_fk1[i], 0u, (unsigned int)(b * Nn + t), o0, o1);
                unsigned int bits = o0 ^ o1;
                float u01 = __uint_as_float((bits >> 9) | 0x3f800000u) - 1.0f;
                float r = fmaxf(TINY, u01 * (1.0f - TINY) + TINY);
                float g = -logf(-logf(r));
                val = logit + g;
            }
        }

        // ---- E: argmax(logit + gumbel), first-index tie break
        rv[t] = val; ri[t] = myn;
        __syncthreads();
        for (int sg = 128; sg; sg >>= 1) {
            if (t < sg) {
                float ov = rv[t + sg]; int oi = ri[t + sg];
                if (ov > rv[t] || (ov == rv[t] && oi < ri[t])) { rv[t] = ov; ri[t] = oi; }
            }
            __syncthreads();
        }
        if (t == 0) sSel = ri[0];
        __syncthreads();
        if (t == sSel) sChosen = logit;

        // ---- F: log_softmax at chosen index
        rv[t] = logit;
        __syncthreads();
        for (int sg = 128; sg; sg >>= 1) {
            if (t < sg) rv[t] = fmaxf(rv[t], rv[t + sg]);
            __syncthreads();
        }
        if (t == 0) sM = rv[0];
        __syncthreads();
        rv[t] = (t < Nn) ? expf(logit - sM) : 0.f;
        __syncthreads();
        for (int sg = 128; sg; sg >>= 1) {
            if (t < sg) rv[t] += rv[t + sg];
            __syncthreads();
        }

        // ---- G: state update + output
        if (t == 0) {
            int sel = sSel;
            sLogp += sChosen - sM - logf(rv[0]);
            sMask[sel] = 1;
            sLast = sel;
            if (i == 0) sFirst = sel;
            if (mode == 0)      ((float*)outp)[(size_t)b * Nn + i] = (float)sel;
            else if (mode == 1) ((int*)outp)[(size_t)b * Nn + i] = sel;
        }
        __syncthreads();
    }

    if (t == 0) {
        if (mode == 0)      ((float*)outp)[(size_t)Bb * Nn + b] = sLogp;
        else if (mode == 2) ((float*)outp)[b] = sLogp;
    }
}

// ---------------------------------------------------------------------------
// Host entry
// ---------------------------------------------------------------------------
extern "C" void kernel_launch(void* const* d_in, const int* in_sizes, int n_in,
                              void* d_out, int out_size) {
    const float* x     = (const float*)d_in[0];
    const float* initK = (const float*)d_in[1];
    const float* initV = (const float*)d_in[2];
    const float* WprjK = (const float*)d_in[3];
    const float* Wq    = (const float*)d_in[4];
    const float* Wk    = (const float*)d_in[5];
    const float* Wv    = (const float*)d_in[6];
    const float* Wo    = (const float*)d_in[7];
    const unsigned int* clipb = (const unsigned int*)d_in[8];

    prep_kernel<<<64, 256>>>(Wk, Wv, WprjK, Wq, Wo, initK, initV);
    gemm_kernel<<<dim3(10, 3200), 256>>>(x);
    hinit_qh_kernel<<<Bb, 128>>>(x, Wq);

    int mode;
    if (out_size >= Bb * Nn + Bb) mode = 0;       // float: visited then logp
    else if (out_size == Bb)      mode = 2;       // float: logp only
    else                          mode = 1;       // int: visited only

    decode_kernel<<<Bb, 256>>>(d_out, mode, clipb);
}